// round 7
// baseline (speedup 1.0000x reference)
#include <cuda_runtime.h>
#include <math.h>

#define BB 32
#define MM 60
#define NN 8400
#define CC 80
#define TILE 128
#define NTILES ((NN + TILE - 1) / TILE)   // 66
#define MT 512                             // k_match threads
#define QCNT 9                             // ceil((NN/2)/MT)
#define NSLOT (2 * QCNT)                   // 18 slots/thread
#define NW (MT / 32)                       // 16 warps
#define INF_COST 1e8f
#define FULL 0xFFFFFFFFu

// Scratch: packed (iou, cost) pairs, [b][m][n]. float4-aligned (NN even).
__device__ float4 g_pack4[(size_t)BB * MM * NN / 2];
__device__ unsigned long long g_mask[(size_t)BB * NN];

__device__ __forceinline__ unsigned int f2o(float f) {
    unsigned int u = __float_as_uint(f);
    return (u & 0x80000000u) ? ~u : (u | 0x80000000u);  // monotonic float->uint
}

// Pass A: per (b, prior-tile) block, 256 threads; halves split the 60 GTs.
__global__ void __launch_bounds__(2 * TILE) k_cost(
        const float* __restrict__ pred_bboxes,
        const float* __restrict__ pred_scores,
        const float* __restrict__ priors,
        const int* __restrict__ gt_labels,
        const float* __restrict__ gt_bboxes,
        const float* __restrict__ pad_flag) {
    int b = blockIdx.y;
    int n0 = blockIdx.x * TILE;
    int tid = threadIdx.x;
    int p = tid & (TILE - 1);
    int half = tid >> 7;
    int n = n0 + p;
    bool inb = (n < NN);

    __shared__ float  s_sc[TILE][CC + 1];     // stride 81: conflict-free
    __shared__ float4 s_gt[MM];
    __shared__ float4 s_gtc[MM];              // cx, cy, a2, label(float bits via int)
    __shared__ float  s_pf[MM];
    __shared__ unsigned char s_v[2][TILE];

    if (tid < MM) {
        float4 g = ((const float4*)gt_bboxes)[b * MM + tid];
        s_gt[tid] = g;
        float4 c;
        c.x = 0.5f * (g.x + g.z);
        c.y = 0.5f * (g.y + g.w);
        c.z = (g.z - g.x) * (g.w - g.y);
        c.w = __int_as_float(gt_labels[b * MM + tid]);
        s_gtc[tid] = c;
        s_pf[tid] = pad_flag[b * MM + tid];
    }
    {
        int rows = min(TILE, NN - n0);
        const float4* src = (const float4*)(pred_scores + ((size_t)b * NN + n0) * CC);
        int tot4 = rows * (CC / 4);
        for (int i = tid; i < tot4; i += 2 * TILE) {
            float4 v = src[i];
            int r = i / (CC / 4), c = (i % (CC / 4)) * 4;
            s_sc[r][c] = v.x; s_sc[r][c + 1] = v.y;
            s_sc[r][c + 2] = v.z; s_sc[r][c + 3] = v.w;
        }
    }
    __syncthreads();

    float4 pb = make_float4(0, 0, 0, 0), pr = make_float4(0, 0, 1, 1);
    if (inb) {
        pb = ((const float4*)pred_bboxes)[(size_t)b * NN + n];
        pr = ((const float4*)priors)[n];
        if (half == 0) g_mask[(size_t)b * NN + n] = 0ull;
    }
    float a1 = (pb.z - pb.x) * (pb.w - pb.y);
    float rstride = __frcp_rn(pr.z);

    int m0 = half * (MM / 2), m1 = m0 + MM / 2;

    {
        bool v = false;
        #pragma unroll 5
        for (int m = m0; m < m1; m++) {
            float4 g = s_gt[m];
            float mn = fminf(fminf(pr.x - g.x, pr.y - g.y), fminf(g.z - pr.x, g.w - pr.y));
            if (mn > 0.f && s_pf[m] > 0.f) v = true;
        }
        s_v[half][p] = v ? 1 : 0;
    }
    __syncthreads();
    bool valid = s_v[0][p] | s_v[1][p];

    float2* gP = (float2*)g_pack4 + ((size_t)b * MM) * NN + n;

    for (int m = m0; m < m1; m++) {
        float4 g = s_gt[m];
        float lx = fmaxf(pb.x, g.x), ly = fmaxf(pb.y, g.y);
        float rx = fminf(pb.z, g.z), ry = fminf(pb.w, g.w);
        float iw = fmaxf(rx - lx, 0.f), ih = fmaxf(ry - ly, 0.f);
        float inter = iw * ih;
        float4 c = s_gtc[m];
        float uni = fmaxf(a1 + c.z - inter, 1e-6f);
        float iou = __fdividef(inter, uni);

        float cost = INF_COST;
        if (valid) {
            float dx = pr.x - c.x, dy = pr.y - c.y;
            float d2 = dx * dx + dy * dy;
            float dist = (d2 > 0.f) ? d2 * rsqrtf(d2) * rstride : 0.f;
            float soft = __exp10f(dist - 3.0f);
            float iou_cost = -3.0f * __logf(iou + 1e-7f);
            float t = s_sc[p][__float_as_int(c.w)];
            float e = __expf(-fabsf(t));
            float r = __fdividef(1.f, 1.f + e);
            float sig = (t >= 0.f) ? r : e * r;
            float bce = fmaxf(t, 0.f) - t * iou + __logf(1.f + e);
            float sc = iou - sig;
            cost = fmaf(bce * sc, sc, iou_cost + soft);
        }
        if (inb) gP[(size_t)m * NN] = make_float2(iou, cost);
    }
}

// Pass B: per (b,m) valid GT, 512 threads. ONE load pass: float4 = 2 packed
// (iou,cost) pairs; both phases run from registers.
__global__ void __launch_bounds__(MT) k_match(const float* __restrict__ pad_flag) {
    int bm = blockIdx.x;
    int b = bm / MM, m = bm % MM;
    if (pad_flag[bm] <= 0.f) return;
    int tid = threadIdx.x;
    int lane = tid & 31, wid = tid >> 5;

    __shared__ unsigned long long s_cand[NW * 13];
    __shared__ int s_ks;

    unsigned int ki[NSLOT], kc[NSLOT];
    {
        const float4* gP = g_pack4 + (size_t)bm * (NN / 2);
        #pragma unroll
        for (int j = 0; j < QCNT; j++) {
            int q = tid + MT * j;
            if (q < NN / 2) {
                float4 v = gP[q];
                ki[2 * j]     = f2o(v.x); kc[2 * j]     = f2o(v.y);
                ki[2 * j + 1] = f2o(v.z); kc[2 * j + 1] = f2o(v.w);
            } else {
                ki[2 * j] = 0u;           kc[2 * j] = 0xFFFFFFFFu;
                ki[2 * j + 1] = 0u;       kc[2 * j + 1] = 0xFFFFFFFFu;
            }
        }
    }
    // n for slot s: q = tid + MT*(s>>1), n = 2q + (s&1)
    #define SLOT_N(s) ((unsigned)(((tid + MT * ((s) >> 1)) << 1) | ((s) & 1)))

    // ---- Phase 1: top-13 iou (descending) ----
    {
        unsigned int used = 0, myv = 0;
        int myj = 0;
        #pragma unroll
        for (int s = 0; s < NSLOT; s++)
            if (ki[s] > myv) { myv = ki[s]; myj = s; }
        for (int it = 0; it < 13; it++) {
            unsigned long long my = ((unsigned long long)myv << 32) | SLOT_N(myj);
            if (myv == 0u) my = 0ull;
            unsigned long long w = my;
            #pragma unroll
            for (int off = 16; off; off >>= 1) {
                unsigned long long o = __shfl_xor_sync(FULL, w, off);
                if (o > w) w = o;
            }
            if (my == w && w != 0ull) {           // unique winner (n embedded)
                used |= 1u << myj;
                myv = 0u; myj = 0;
                #pragma unroll
                for (int s = 0; s < NSLOT; s++)
                    if (!((used >> s) & 1u) && ki[s] > myv) { myv = ki[s]; myj = s; }
            }
            if (lane == 0) s_cand[wid * 13 + it] = w;
        }
    }
    __syncthreads();

    // warp 0 merges NW*13 = 208 unique candidates -> dynamic_ks
    if (wid == 0) {
        unsigned long long c[7];
        #pragma unroll
        for (int r = 0; r < 7; r++) {
            int i = lane + 32 * r;
            c[r] = (i < NW * 13) ? s_cand[i] : 0ull;
        }
        int used7 = 0;
        float sum = 0.f;
        for (int it = 0; it < 13; it++) {
            unsigned long long mk = 0ull; int mr = 0;
            #pragma unroll
            for (int r = 0; r < 7; r++)
                if (!((used7 >> r) & 1) && c[r] > mk) { mk = c[r]; mr = r; }
            unsigned long long w = mk;
            #pragma unroll
            for (int off = 16; off; off >>= 1) {
                unsigned long long o = __shfl_xor_sync(FULL, w, off);
                if (o > w) w = o;
            }
            if (mk == w && w != 0ull) used7 |= 1 << mr;
            sum += __uint_as_float((unsigned)(w >> 32) ^ 0x80000000u);  // iou >= 0
        }
        int ks = (int)sum;               // trunc toward 0, matches astype(int32)
        if (ks < 1) ks = 1;
        if (ks > 13) ks = 13;
        if (lane == 0) s_ks = ks;
    }
    __syncthreads();
    int ks = s_ks;

    // ---- Phase 2: bottom-ks cost (ascending, lowest n wins ties) ----
    {
        unsigned int used = 0, myv = 0xFFFFFFFFu;
        int myj = 0;
        #pragma unroll
        for (int s = 0; s < NSLOT; s++)
            if (kc[s] < myv) { myv = kc[s]; myj = s; }
        for (int it = 0; it < ks; it++) {
            unsigned long long my = ((unsigned long long)myv << 32) | SLOT_N(myj);
            if (myv == 0xFFFFFFFFu) my = ~0ull;
            unsigned long long w = my;
            #pragma unroll
            for (int off = 16; off; off >>= 1) {
                unsigned long long o = __shfl_xor_sync(FULL, w, off);
                if (o < w) w = o;
            }
            if (my == w && w != ~0ull) {
                used |= 1u << myj;
                myv = 0xFFFFFFFFu; myj = 0;
                #pragma unroll
                for (int s = 0; s < NSLOT; s++)
                    if (!((used >> s) & 1u) && kc[s] < myv) { myv = kc[s]; myj = s; }
            }
            if (lane == 0) s_cand[wid * 13 + it] = w;
        }
    }
    __syncthreads();

    if (wid == 0) {
        unsigned long long c[7];
        #pragma unroll
        for (int r = 0; r < 7; r++) {
            int i = lane + 32 * r;
            c[r] = (i < NW * 13 && (i % 13) < ks) ? s_cand[i] : ~0ull;
        }
        int used7 = 0;
        for (int it = 0; it < ks; it++) {
            unsigned long long mk = ~0ull; int mr = 0;
            #pragma unroll
            for (int r = 0; r < 7; r++)
                if (!((used7 >> r) & 1) && c[r] < mk) { mk = c[r]; mr = r; }
            unsigned long long w = mk;
            #pragma unroll
            for (int off = 16; off; off >>= 1) {
                unsigned long long o = __shfl_xor_sync(FULL, w, off);
                if (o < w) w = o;
            }
            if (mk == w && w != ~0ull) used7 |= 1 << mr;
            if (lane == 0)
                atomicOr(&g_mask[(size_t)b * NN + (unsigned)(w & 0xFFFFFFFFu)], 1ull << m);
        }
    }
    #undef SLOT_N
}

// Pass C: per (b, n) resolve multi-matches, emit all 4 outputs.
__global__ void k_out(const int* __restrict__ gt_labels,
                      const float* __restrict__ gt_bboxes,
                      float* __restrict__ out) {
    int idx = blockIdx.x * blockDim.x + threadIdx.x;
    if (idx >= BB * NN) return;
    int b = idx / NN, n = idx % NN;
    const float* P = (const float*)g_pack4;   // pairs: [2*k]=iou, [2*k+1]=cost

    unsigned long long mask = g_mask[idx];
    if (__popcll(mask) > 1) {
        unsigned int bo = 0xFFFFFFFFu;
        int am = 0;
        for (int m = 0; m < MM; m++) {
            unsigned int o = f2o(P[(((size_t)b * MM + m) * NN + n) * 2 + 1]);
            if (o < bo) { bo = o; am = m; }
        }
        mask = 1ull << am;
    }
    bool fg = (mask != 0ull);
    int matched = fg ? (__ffsll((long long)mask) - 1) : 0;

    float lab = fg ? (float)gt_labels[b * MM + matched] : (float)CC;
    float metric = fg ? P[(((size_t)b * MM + matched) * NN + n) * 2] : 0.f;
    float4 bb = make_float4(0.f, 0.f, 0.f, 0.f);
    if (fg) bb = ((const float4*)gt_bboxes)[b * MM + matched];

    size_t S = (size_t)BB * NN;
    out[idx] = lab;
    out[S + idx] = 1.0f;
    ((float4*)(out + 2 * S))[idx] = bb;
    out[6 * S + idx] = metric;
}

extern "C" void kernel_launch(void* const* d_in, const int* in_sizes, int n_in,
                              void* d_out, int out_size) {
    const float* pred_bboxes = (const float*)d_in[0];
    const float* pred_scores = (const float*)d_in[1];
    const float* priors      = (const float*)d_in[2];
    const int*   gt_labels   = (const int*)d_in[3];
    const float* gt_bboxes   = (const float*)d_in[4];
    const float* pad_flag    = (const float*)d_in[5];
    float* out = (float*)d_out;

    dim3 gc(NTILES, BB);
    k_cost<<<gc, 2 * TILE>>>(pred_bboxes, pred_scores, priors,
                             gt_labels, gt_bboxes, pad_flag);

    k_match<<<BB * MM, MT>>>(pad_flag);

    k_out<<<(BB * NN + 255) / 256, 256>>>(gt_labels, gt_bboxes, out);
}

// round 8
// speedup vs baseline: 1.0024x; 1.0024x over previous
#include <cuda_runtime.h>
#include <math.h>

#define BB 32
#define MM 60
#define NN 8400
#define CC 80
#define TILE 128
#define NTILES ((NN + TILE - 1) / TILE)   // 66
#define MT 512                             // k_match threads
#define QCNT 9                             // ceil((NN/2)/MT)
#define NSLOT (2 * QCNT)                   // 18 slots/thread
#define NW (MT / 32)                       // 16 warps
#define INF_COST 1e8f
#define FULL 0xFFFFFFFFu

// Scratch: packed (iou, cost) pairs, [b][m][n]. float4-aligned (NN even).
__device__ float4 g_pack4[(size_t)BB * MM * NN / 2];
__device__ unsigned long long g_mask[(size_t)BB * NN];

__device__ __forceinline__ unsigned int f2o(float f) {
    unsigned int u = __float_as_uint(f);
    return (u & 0x80000000u) ? ~u : (u | 0x80000000u);  // monotonic float->uint
}

// Pass A: per (b, prior-tile) block, 256 threads; halves split the 60 GTs.
__global__ void __launch_bounds__(2 * TILE) k_cost(
        const float* __restrict__ pred_bboxes,
        const float* __restrict__ pred_scores,
        const float* __restrict__ priors,
        const int* __restrict__ gt_labels,
        const float* __restrict__ gt_bboxes,
        const float* __restrict__ pad_flag) {
    int b = blockIdx.y;
    int n0 = blockIdx.x * TILE;
    int tid = threadIdx.x;
    int p = tid & (TILE - 1);
    int half = tid >> 7;
    int n = n0 + p;
    bool inb = (n < NN);

    __shared__ float  s_sc[TILE][CC + 1];     // stride 81: conflict-free
    __shared__ float4 s_gt[MM];
    __shared__ float4 s_gtc[MM];              // cx, cy, a2, label(float bits via int)
    __shared__ float  s_pf[MM];
    __shared__ unsigned char s_v[2][TILE];

    if (tid < MM) {
        float4 g = ((const float4*)gt_bboxes)[b * MM + tid];
        s_gt[tid] = g;
        float4 c;
        c.x = 0.5f * (g.x + g.z);
        c.y = 0.5f * (g.y + g.w);
        c.z = (g.z - g.x) * (g.w - g.y);
        c.w = __int_as_float(gt_labels[b * MM + tid]);
        s_gtc[tid] = c;
        s_pf[tid] = pad_flag[b * MM + tid];
    }
    {
        int rows = min(TILE, NN - n0);
        const float4* src = (const float4*)(pred_scores + ((size_t)b * NN + n0) * CC);
        int tot4 = rows * (CC / 4);
        for (int i = tid; i < tot4; i += 2 * TILE) {
            float4 v = src[i];
            int r = i / (CC / 4), c = (i % (CC / 4)) * 4;
            s_sc[r][c] = v.x; s_sc[r][c + 1] = v.y;
            s_sc[r][c + 2] = v.z; s_sc[r][c + 3] = v.w;
        }
    }
    __syncthreads();

    float4 pb = make_float4(0, 0, 0, 0), pr = make_float4(0, 0, 1, 1);
    if (inb) {
        pb = ((const float4*)pred_bboxes)[(size_t)b * NN + n];
        pr = ((const float4*)priors)[n];
        if (half == 0) g_mask[(size_t)b * NN + n] = 0ull;
    }
    float a1 = (pb.z - pb.x) * (pb.w - pb.y);
    float rstride = __frcp_rn(pr.z);

    int m0 = half * (MM / 2), m1 = m0 + MM / 2;

    {
        bool v = false;
        #pragma unroll 5
        for (int m = m0; m < m1; m++) {
            float4 g = s_gt[m];
            float mn = fminf(fminf(pr.x - g.x, pr.y - g.y), fminf(g.z - pr.x, g.w - pr.y));
            if (mn > 0.f && s_pf[m] > 0.f) v = true;
        }
        s_v[half][p] = v ? 1 : 0;
    }
    __syncthreads();
    bool valid = s_v[0][p] | s_v[1][p];

    float2* gP = (float2*)g_pack4 + ((size_t)b * MM) * NN + n;

    for (int m = m0; m < m1; m++) {
        float4 g = s_gt[m];
        float lx = fmaxf(pb.x, g.x), ly = fmaxf(pb.y, g.y);
        float rx = fminf(pb.z, g.z), ry = fminf(pb.w, g.w);
        float iw = fmaxf(rx - lx, 0.f), ih = fmaxf(ry - ly, 0.f);
        float inter = iw * ih;
        float4 c = s_gtc[m];
        float uni = fmaxf(a1 + c.z - inter, 1e-6f);
        float iou = __fdividef(inter, uni);

        float cost = INF_COST;
        if (valid) {
            float dx = pr.x - c.x, dy = pr.y - c.y;
            float d2 = dx * dx + dy * dy;
            float dist = (d2 > 0.f) ? d2 * rsqrtf(d2) * rstride : 0.f;
            float soft = __exp10f(dist - 3.0f);
            float iou_cost = -3.0f * __logf(iou + 1e-7f);
            float t = s_sc[p][__float_as_int(c.w)];
            float e = __expf(-fabsf(t));
            float r = __fdividef(1.f, 1.f + e);
            float sig = (t >= 0.f) ? r : e * r;
            float bce = fmaxf(t, 0.f) - t * iou + __logf(1.f + e);
            float sc = iou - sig;
            cost = fmaf(bce * sc, sc, iou_cost + soft);
        }
        if (inb) gP[(size_t)m * NN] = make_float2(iou, cost);
    }
}

// Pass B: per (b,m) valid GT, 512 threads. ONE load pass: float4 = 2 packed
// (iou,cost) pairs; both phases run from registers.
__global__ void __launch_bounds__(MT) k_match(const float* __restrict__ pad_flag) {
    int bm = blockIdx.x;
    int b = bm / MM, m = bm % MM;
    if (pad_flag[bm] <= 0.f) return;
    int tid = threadIdx.x;
    int lane = tid & 31, wid = tid >> 5;

    __shared__ unsigned long long s_cand[NW * 13];
    __shared__ int s_ks;

    unsigned int ki[NSLOT], kc[NSLOT];
    {
        const float4* gP = g_pack4 + (size_t)bm * (NN / 2);
        #pragma unroll
        for (int j = 0; j < QCNT; j++) {
            int q = tid + MT * j;
            if (q < NN / 2) {
                float4 v = gP[q];
                ki[2 * j]     = f2o(v.x); kc[2 * j]     = f2o(v.y);
                ki[2 * j + 1] = f2o(v.z); kc[2 * j + 1] = f2o(v.w);
            } else {
                ki[2 * j] = 0u;           kc[2 * j] = 0xFFFFFFFFu;
                ki[2 * j + 1] = 0u;       kc[2 * j + 1] = 0xFFFFFFFFu;
            }
        }
    }
    // n for slot s: q = tid + MT*(s>>1), n = 2q + (s&1)
    #define SLOT_N(s) ((unsigned)(((tid + MT * ((s) >> 1)) << 1) | ((s) & 1)))

    // ---- Phase 1: top-13 iou (descending) ----
    {
        unsigned int used = 0, myv = 0;
        int myj = 0;
        #pragma unroll
        for (int s = 0; s < NSLOT; s++)
            if (ki[s] > myv) { myv = ki[s]; myj = s; }
        for (int it = 0; it < 13; it++) {
            unsigned long long my = ((unsigned long long)myv << 32) | SLOT_N(myj);
            if (myv == 0u) my = 0ull;
            unsigned long long w = my;
            #pragma unroll
            for (int off = 16; off; off >>= 1) {
                unsigned long long o = __shfl_xor_sync(FULL, w, off);
                if (o > w) w = o;
            }
            if (my == w && w != 0ull) {           // unique winner (n embedded)
                used |= 1u << myj;
                myv = 0u; myj = 0;
                #pragma unroll
                for (int s = 0; s < NSLOT; s++)
                    if (!((used >> s) & 1u) && ki[s] > myv) { myv = ki[s]; myj = s; }
            }
            if (lane == 0) s_cand[wid * 13 + it] = w;
        }
    }
    __syncthreads();

    // warp 0 merges NW*13 = 208 unique candidates -> dynamic_ks
    if (wid == 0) {
        unsigned long long c[7];
        #pragma unroll
        for (int r = 0; r < 7; r++) {
            int i = lane + 32 * r;
            c[r] = (i < NW * 13) ? s_cand[i] : 0ull;
        }
        int used7 = 0;
        float sum = 0.f;
        for (int it = 0; it < 13; it++) {
            unsigned long long mk = 0ull; int mr = 0;
            #pragma unroll
            for (int r = 0; r < 7; r++)
                if (!((used7 >> r) & 1) && c[r] > mk) { mk = c[r]; mr = r; }
            unsigned long long w = mk;
            #pragma unroll
            for (int off = 16; off; off >>= 1) {
                unsigned long long o = __shfl_xor_sync(FULL, w, off);
                if (o > w) w = o;
            }
            if (mk == w && w != 0ull) used7 |= 1 << mr;
            sum += __uint_as_float((unsigned)(w >> 32) ^ 0x80000000u);  // iou >= 0
        }
        int ks = (int)sum;               // trunc toward 0, matches astype(int32)
        if (ks < 1) ks = 1;
        if (ks > 13) ks = 13;
        if (lane == 0) s_ks = ks;
    }
    __syncthreads();
    int ks = s_ks;

    // ---- Phase 2: bottom-ks cost (ascending, lowest n wins ties) ----
    {
        unsigned int used = 0, myv = 0xFFFFFFFFu;
        int myj = 0;
        #pragma unroll
        for (int s = 0; s < NSLOT; s++)
            if (kc[s] < myv) { myv = kc[s]; myj = s; }
        for (int it = 0; it < ks; it++) {
            unsigned long long my = ((unsigned long long)myv << 32) | SLOT_N(myj);
            if (myv == 0xFFFFFFFFu) my = ~0ull;
            unsigned long long w = my;
            #pragma unroll
            for (int off = 16; off; off >>= 1) {
                unsigned long long o = __shfl_xor_sync(FULL, w, off);
                if (o < w) w = o;
            }
            if (my == w && w != ~0ull) {
                used |= 1u << myj;
                myv = 0xFFFFFFFFu; myj = 0;
                #pragma unroll
                for (int s = 0; s < NSLOT; s++)
                    if (!((used >> s) & 1u) && kc[s] < myv) { myv = kc[s]; myj = s; }
            }
            if (lane == 0) s_cand[wid * 13 + it] = w;
        }
    }
    __syncthreads();

    if (wid == 0) {
        unsigned long long c[7];
        #pragma unroll
        for (int r = 0; r < 7; r++) {
            int i = lane + 32 * r;
            c[r] = (i < NW * 13 && (i % 13) < ks) ? s_cand[i] : ~0ull;
        }
        int used7 = 0;
        for (int it = 0; it < ks; it++) {
            unsigned long long mk = ~0ull; int mr = 0;
            #pragma unroll
            for (int r = 0; r < 7; r++)
                if (!((used7 >> r) & 1) && c[r] < mk) { mk = c[r]; mr = r; }
            unsigned long long w = mk;
            #pragma unroll
            for (int off = 16; off; off >>= 1) {
                unsigned long long o = __shfl_xor_sync(FULL, w, off);
                if (o < w) w = o;
            }
            if (mk == w && w != ~0ull) used7 |= 1 << mr;
            if (lane == 0)
                atomicOr(&g_mask[(size_t)b * NN + (unsigned)(w & 0xFFFFFFFFu)], 1ull << m);
        }
    }
    #undef SLOT_N
}

// Pass C: per (b, n) resolve multi-matches, emit all 4 outputs.
__global__ void k_out(const int* __restrict__ gt_labels,
                      const float* __restrict__ gt_bboxes,
                      float* __restrict__ out) {
    int idx = blockIdx.x * blockDim.x + threadIdx.x;
    if (idx >= BB * NN) return;
    int b = idx / NN, n = idx % NN;
    const float* P = (const float*)g_pack4;   // pairs: [2*k]=iou, [2*k+1]=cost

    unsigned long long mask = g_mask[idx];
    if (__popcll(mask) > 1) {
        unsigned int bo = 0xFFFFFFFFu;
        int am = 0;
        for (int m = 0; m < MM; m++) {
            unsigned int o = f2o(P[(((size_t)b * MM + m) * NN + n) * 2 + 1]);
            if (o < bo) { bo = o; am = m; }
        }
        mask = 1ull << am;
    }
    bool fg = (mask != 0ull);
    int matched = fg ? (__ffsll((long long)mask) - 1) : 0;

    float lab = fg ? (float)gt_labels[b * MM + matched] : (float)CC;
    float metric = fg ? P[(((size_t)b * MM + matched) * NN + n) * 2] : 0.f;
    float4 bb = make_float4(0.f, 0.f, 0.f, 0.f);
    if (fg) bb = ((const float4*)gt_bboxes)[b * MM + matched];

    size_t S = (size_t)BB * NN;
    out[idx] = lab;
    out[S + idx] = 1.0f;
    ((float4*)(out + 2 * S))[idx] = bb;
    out[6 * S + idx] = metric;
}

extern "C" void kernel_launch(void* const* d_in, const int* in_sizes, int n_in,
                              void* d_out, int out_size) {
    const float* pred_bboxes = (const float*)d_in[0];
    const float* pred_scores = (const float*)d_in[1];
    const float* priors      = (const float*)d_in[2];
    const int*   gt_labels   = (const int*)d_in[3];
    const float* gt_bboxes   = (const float*)d_in[4];
    const float* pad_flag    = (const float*)d_in[5];
    float* out = (float*)d_out;

    dim3 gc(NTILES, BB);
    k_cost<<<gc, 2 * TILE>>>(pred_bboxes, pred_scores, priors,
                             gt_labels, gt_bboxes, pad_flag);

    k_match<<<BB * MM, MT>>>(pad_flag);

    k_out<<<(BB * NN + 255) / 256, 256>>>(gt_labels, gt_bboxes, out);
}

// round 9
// speedup vs baseline: 1.0053x; 1.0029x over previous
#include <cuda_runtime.h>
#include <math.h>

#define BB 32
#define MM 60
#define NN 8400
#define CC 80
#define TILE 128
#define NTILES ((NN + TILE - 1) / TILE)   // 66
#define MT 512                             // k_match threads
#define QCNT 9                             // ceil((NN/2)/MT)
#define NSLOT (2 * QCNT)                   // 18 slots/thread
#define NW (MT / 32)                       // 16 warps
#define INF_COST 1e8f
#define FULL 0xFFFFFFFFu

// Scratch: packed (iou, cost) pairs, [b][m][n]. float4-aligned (NN even).
__device__ float4 g_pack4[(size_t)BB * MM * NN / 2];
__device__ unsigned long long g_mask[(size_t)BB * NN];

__device__ __forceinline__ unsigned int f2o(float f) {
    unsigned int u = __float_as_uint(f);
    return (u & 0x80000000u) ? ~u : (u | 0x80000000u);  // monotonic float->uint
}

// Pass A: per (b, prior-tile) block, 256 threads; halves split the 60 GTs.
__global__ void __launch_bounds__(2 * TILE) k_cost(
        const float* __restrict__ pred_bboxes,
        const float* __restrict__ pred_scores,
        const float* __restrict__ priors,
        const int* __restrict__ gt_labels,
        const float* __restrict__ gt_bboxes,
        const float* __restrict__ pad_flag) {
    int b = blockIdx.y;
    int n0 = blockIdx.x * TILE;
    int tid = threadIdx.x;
    int p = tid & (TILE - 1);
    int half = tid >> 7;
    int n = n0 + p;
    bool inb = (n < NN);

    __shared__ float  s_sc[TILE][CC + 1];     // stride 81: conflict-free
    __shared__ float4 s_gt[MM];
    __shared__ float4 s_gtc[MM];              // cx, cy, a2, label(float bits via int)
    __shared__ float  s_pf[MM];
    __shared__ unsigned char s_v[2][TILE];

    if (tid < MM) {
        float4 g = ((const float4*)gt_bboxes)[b * MM + tid];
        s_gt[tid] = g;
        float4 c;
        c.x = 0.5f * (g.x + g.z);
        c.y = 0.5f * (g.y + g.w);
        c.z = (g.z - g.x) * (g.w - g.y);
        c.w = __int_as_float(gt_labels[b * MM + tid]);
        s_gtc[tid] = c;
        s_pf[tid] = pad_flag[b * MM + tid];
    }
    {
        int rows = min(TILE, NN - n0);
        const float4* src = (const float4*)(pred_scores + ((size_t)b * NN + n0) * CC);
        int tot4 = rows * (CC / 4);
        for (int i = tid; i < tot4; i += 2 * TILE) {
            float4 v = src[i];
            int r = i / (CC / 4), c = (i % (CC / 4)) * 4;
            s_sc[r][c] = v.x; s_sc[r][c + 1] = v.y;
            s_sc[r][c + 2] = v.z; s_sc[r][c + 3] = v.w;
        }
    }
    __syncthreads();

    float4 pb = make_float4(0, 0, 0, 0), pr = make_float4(0, 0, 1, 1);
    if (inb) {
        pb = ((const float4*)pred_bboxes)[(size_t)b * NN + n];
        pr = ((const float4*)priors)[n];
        if (half == 0) g_mask[(size_t)b * NN + n] = 0ull;
    }
    float a1 = (pb.z - pb.x) * (pb.w - pb.y);
    float rstride = __frcp_rn(pr.z);

    int m0 = half * (MM / 2), m1 = m0 + MM / 2;

    {
        bool v = false;
        #pragma unroll 5
        for (int m = m0; m < m1; m++) {
            float4 g = s_gt[m];
            float mn = fminf(fminf(pr.x - g.x, pr.y - g.y), fminf(g.z - pr.x, g.w - pr.y));
            if (mn > 0.f && s_pf[m] > 0.f) v = true;
        }
        s_v[half][p] = v ? 1 : 0;
    }
    __syncthreads();
    bool valid = s_v[0][p] | s_v[1][p];

    float2* gP = (float2*)g_pack4 + ((size_t)b * MM) * NN + n;

    for (int m = m0; m < m1; m++) {
        float4 g = s_gt[m];
        float lx = fmaxf(pb.x, g.x), ly = fmaxf(pb.y, g.y);
        float rx = fminf(pb.z, g.z), ry = fminf(pb.w, g.w);
        float iw = fmaxf(rx - lx, 0.f), ih = fmaxf(ry - ly, 0.f);
        float inter = iw * ih;
        float4 c = s_gtc[m];
        float uni = fmaxf(a1 + c.z - inter, 1e-6f);
        float iou = __fdividef(inter, uni);

        float cost = INF_COST;
        if (valid) {
            float dx = pr.x - c.x, dy = pr.y - c.y;
            float d2 = dx * dx + dy * dy;
            float dist = (d2 > 0.f) ? d2 * rsqrtf(d2) * rstride : 0.f;
            float soft = __exp10f(dist - 3.0f);
            float iou_cost = -3.0f * __logf(iou + 1e-7f);
            float t = s_sc[p][__float_as_int(c.w)];
            float e = __expf(-fabsf(t));
            float r = __fdividef(1.f, 1.f + e);
            float sig = (t >= 0.f) ? r : e * r;
            float bce = fmaxf(t, 0.f) - t * iou + __logf(1.f + e);
            float sc = iou - sig;
            cost = fmaf(bce * sc, sc, iou_cost + soft);
        }
        if (inb) gP[(size_t)m * NN] = make_float2(iou, cost);
    }
}

// Pass B: per (b,m) valid GT, 512 threads. ONE load pass: float4 = 2 packed
// (iou,cost) pairs; both phases run from registers.
__global__ void __launch_bounds__(MT) k_match(const float* __restrict__ pad_flag) {
    int bm = blockIdx.x;
    int b = bm / MM, m = bm % MM;
    if (pad_flag[bm] <= 0.f) return;
    int tid = threadIdx.x;
    int lane = tid & 31, wid = tid >> 5;

    __shared__ unsigned long long s_cand[NW * 13];
    __shared__ int s_ks;

    unsigned int ki[NSLOT], kc[NSLOT];
    {
        const float4* gP = g_pack4 + (size_t)bm * (NN / 2);
        #pragma unroll
        for (int j = 0; j < QCNT; j++) {
            int q = tid + MT * j;
            if (q < NN / 2) {
                float4 v = gP[q];
                ki[2 * j]     = f2o(v.x); kc[2 * j]     = f2o(v.y);
                ki[2 * j + 1] = f2o(v.z); kc[2 * j + 1] = f2o(v.w);
            } else {
                ki[2 * j] = 0u;           kc[2 * j] = 0xFFFFFFFFu;
                ki[2 * j + 1] = 0u;       kc[2 * j + 1] = 0xFFFFFFFFu;
            }
        }
    }
    // n for slot s: q = tid + MT*(s>>1), n = 2q + (s&1)
    #define SLOT_N(s) ((unsigned)(((tid + MT * ((s) >> 1)) << 1) | ((s) & 1)))

    // ---- Phase 1: top-13 iou (descending) ----
    {
        unsigned int used = 0, myv = 0;
        int myj = 0;
        #pragma unroll
        for (int s = 0; s < NSLOT; s++)
            if (ki[s] > myv) { myv = ki[s]; myj = s; }
        for (int it = 0; it < 13; it++) {
            unsigned long long my = ((unsigned long long)myv << 32) | SLOT_N(myj);
            if (myv == 0u) my = 0ull;
            unsigned long long w = my;
            #pragma unroll
            for (int off = 16; off; off >>= 1) {
                unsigned long long o = __shfl_xor_sync(FULL, w, off);
                if (o > w) w = o;
            }
            if (my == w && w != 0ull) {           // unique winner (n embedded)
                used |= 1u << myj;
                myv = 0u; myj = 0;
                #pragma unroll
                for (int s = 0; s < NSLOT; s++)
                    if (!((used >> s) & 1u) && ki[s] > myv) { myv = ki[s]; myj = s; }
            }
            if (lane == 0) s_cand[wid * 13 + it] = w;
        }
    }
    __syncthreads();

    // warp 0 merges NW*13 = 208 unique candidates -> dynamic_ks
    if (wid == 0) {
        unsigned long long c[7];
        #pragma unroll
        for (int r = 0; r < 7; r++) {
            int i = lane + 32 * r;
            c[r] = (i < NW * 13) ? s_cand[i] : 0ull;
        }
        int used7 = 0;
        float sum = 0.f;
        for (int it = 0; it < 13; it++) {
            unsigned long long mk = 0ull; int mr = 0;
            #pragma unroll
            for (int r = 0; r < 7; r++)
                if (!((used7 >> r) & 1) && c[r] > mk) { mk = c[r]; mr = r; }
            unsigned long long w = mk;
            #pragma unroll
            for (int off = 16; off; off >>= 1) {
                unsigned long long o = __shfl_xor_sync(FULL, w, off);
                if (o > w) w = o;
            }
            if (mk == w && w != 0ull) used7 |= 1 << mr;
            sum += __uint_as_float((unsigned)(w >> 32) ^ 0x80000000u);  // iou >= 0
        }
        int ks = (int)sum;               // trunc toward 0, matches astype(int32)
        if (ks < 1) ks = 1;
        if (ks > 13) ks = 13;
        if (lane == 0) s_ks = ks;
    }
    __syncthreads();
    int ks = s_ks;

    // ---- Phase 2: bottom-ks cost (ascending, lowest n wins ties) ----
    {
        unsigned int used = 0, myv = 0xFFFFFFFFu;
        int myj = 0;
        #pragma unroll
        for (int s = 0; s < NSLOT; s++)
            if (kc[s] < myv) { myv = kc[s]; myj = s; }
        for (int it = 0; it < ks; it++) {
            unsigned long long my = ((unsigned long long)myv << 32) | SLOT_N(myj);
            if (myv == 0xFFFFFFFFu) my = ~0ull;
            unsigned long long w = my;
            #pragma unroll
            for (int off = 16; off; off >>= 1) {
                unsigned long long o = __shfl_xor_sync(FULL, w, off);
                if (o < w) w = o;
            }
            if (my == w && w != ~0ull) {
                used |= 1u << myj;
                myv = 0xFFFFFFFFu; myj = 0;
                #pragma unroll
                for (int s = 0; s < NSLOT; s++)
                    if (!((used >> s) & 1u) && kc[s] < myv) { myv = kc[s]; myj = s; }
            }
            if (lane == 0) s_cand[wid * 13 + it] = w;
        }
    }
    __syncthreads();

    if (wid == 0) {
        unsigned long long c[7];
        #pragma unroll
        for (int r = 0; r < 7; r++) {
            int i = lane + 32 * r;
            c[r] = (i < NW * 13 && (i % 13) < ks) ? s_cand[i] : ~0ull;
        }
        int used7 = 0;
        for (int it = 0; it < ks; it++) {
            unsigned long long mk = ~0ull; int mr = 0;
            #pragma unroll
            for (int r = 0; r < 7; r++)
                if (!((used7 >> r) & 1) && c[r] < mk) { mk = c[r]; mr = r; }
            unsigned long long w = mk;
            #pragma unroll
            for (int off = 16; off; off >>= 1) {
                unsigned long long o = __shfl_xor_sync(FULL, w, off);
                if (o < w) w = o;
            }
            if (mk == w && w != ~0ull) used7 |= 1 << mr;
            if (lane == 0)
                atomicOr(&g_mask[(size_t)b * NN + (unsigned)(w & 0xFFFFFFFFu)], 1ull << m);
        }
    }
    #undef SLOT_N
}

// Pass C: per (b, n) resolve multi-matches, emit all 4 outputs.
__global__ void k_out(const int* __restrict__ gt_labels,
                      const float* __restrict__ gt_bboxes,
                      float* __restrict__ out) {
    int idx = blockIdx.x * blockDim.x + threadIdx.x;
    if (idx >= BB * NN) return;
    int b = idx / NN, n = idx % NN;
    const float* P = (const float*)g_pack4;   // pairs: [2*k]=iou, [2*k+1]=cost

    unsigned long long mask = g_mask[idx];
    if (__popcll(mask) > 1) {
        unsigned int bo = 0xFFFFFFFFu;
        int am = 0;
        for (int m = 0; m < MM; m++) {
            unsigned int o = f2o(P[(((size_t)b * MM + m) * NN + n) * 2 + 1]);
            if (o < bo) { bo = o; am = m; }
        }
        mask = 1ull << am;
    }
    bool fg = (mask != 0ull);
    int matched = fg ? (__ffsll((long long)mask) - 1) : 0;

    float lab = fg ? (float)gt_labels[b * MM + matched] : (float)CC;
    float metric = fg ? P[(((size_t)b * MM + matched) * NN + n) * 2] : 0.f;
    float4 bb = make_float4(0.f, 0.f, 0.f, 0.f);
    if (fg) bb = ((const float4*)gt_bboxes)[b * MM + matched];

    size_t S = (size_t)BB * NN;
    out[idx] = lab;
    out[S + idx] = 1.0f;
    ((float4*)(out + 2 * S))[idx] = bb;
    out[6 * S + idx] = metric;
}

extern "C" void kernel_launch(void* const* d_in, const int* in_sizes, int n_in,
                              void* d_out, int out_size) {
    const float* pred_bboxes = (const float*)d_in[0];
    const float* pred_scores = (const float*)d_in[1];
    const float* priors      = (const float*)d_in[2];
    const int*   gt_labels   = (const int*)d_in[3];
    const float* gt_bboxes   = (const float*)d_in[4];
    const float* pad_flag    = (const float*)d_in[5];
    float* out = (float*)d_out;

    dim3 gc(NTILES, BB);
    k_cost<<<gc, 2 * TILE>>>(pred_bboxes, pred_scores, priors,
                             gt_labels, gt_bboxes, pad_flag);

    k_match<<<BB * MM, MT>>>(pad_flag);

    k_out<<<(BB * NN + 255) / 256, 256>>>(gt_labels, gt_bboxes, out);
}